// round 7
// baseline (speedup 1.0000x reference)
#include <cuda_runtime.h>
#include <cstdint>

// MinimalRSNN: GLIF3 + AlphaPSC recurrent SNN.
//   Phase A: I_ext = x @ W_in^T  (fp32 SGEMM, 128x128x8, f32x2 packed FMA)
//   Phase B: persistent 1000-step scan, 128 CTAs
//            - warp tile 8b x 4h, K-split 32, f32x2 accumulators
//            - bf16 spike transport, prefetch-depth-2 register pipeline
//            - distributed 16-counter grid barrier, release-atomic arrive
//   Phase C: out = spike_rate @ W_out^T
// Launch order pads scan_kernel to index 5 so ncu (-s 5 -c 1) captures it.

#define T_STEPS 1000
#define BATCH   32
#define NI      512
#define NH      1024
#define NO      256

#define V_TH   (-45.0f)
#define V_RST  (-60.0f)
#define D_SYN  0.8187307530779818f
#define D_A0   0.9048374180359595f
#define D_A1   0.8187307530779818f

#define NBLK   128
#define NCTR   16
#define CPC    (NBLK / NCTR)

#define FMA2(d, a, b)  asm("fma.rn.f32x2 %0, %1, %2, %0;" : "+l"(d) : "l"(a), "l"(b))
#define PACK2(d, lo, hi) asm("mov.b64 %0, {%1, %2};" : "=l"(d) : "r"(lo), "r"(hi))
#define UNPK2(lo, hi, s) asm("mov.b64 {%0, %1}, %2;" : "=r"(lo), "=r"(hi) : "l"(s))

typedef unsigned long long u64;
typedef unsigned int       u32;

// -------- device scratch (no allocations allowed) --------
__device__ float          g_Iext[(size_t)T_STEPS * BATCH * NH];   // 131 MB
__device__ unsigned short g_spk16[2][BATCH * NH];                 // bf16 spikes
__device__ float          g_rate[BATCH * NH];
__device__ unsigned int   g_bars[NCTR][64];                       // 256B apart

__global__ void init_kernel() {
    if (threadIdx.x < NCTR) g_bars[threadIdx.x][0] = 0u;
}

// -------- Phase A: C[M,N] = A[M,K] * B[N,K]^T (fp32, f32x2 inner) --------
#define BM 128
#define BN 128
#define BK 8
__global__ __launch_bounds__(256, 2) void gemm_in_kernel(const float* __restrict__ A,
                                                         const float* __restrict__ Bm) {
    __shared__ float As[BK][BM];
    __shared__ float Bs[BK][BN];
    const int tid = threadIdx.x;
    const int m0 = blockIdx.y * BM, n0 = blockIdx.x * BN;
    const int lr = tid >> 1;
    const int lc = (tid & 1) * 4;
    const int tx = tid & 15, ty = tid >> 4;
    u64 acc[8][4];
#pragma unroll
    for (int i = 0; i < 8; i++)
#pragma unroll
        for (int j = 0; j < 4; j++) acc[i][j] = 0ull;

    for (int kc = 0; kc < NI; kc += BK) {
        float4 av = *(const float4*)&A [(size_t)(m0 + lr) * NI + kc + lc];
        float4 bv = *(const float4*)&Bm[(size_t)(n0 + lr) * NI + kc + lc];
        As[lc + 0][lr] = av.x; As[lc + 1][lr] = av.y;
        As[lc + 2][lr] = av.z; As[lc + 3][lr] = av.w;
        Bs[lc + 0][lr] = bv.x; Bs[lc + 1][lr] = bv.y;
        Bs[lc + 2][lr] = bv.z; Bs[lc + 3][lr] = bv.w;
        __syncthreads();
#pragma unroll
        for (int k = 0; k < BK; k++) {
            float4 a0 = *(const float4*)&As[k][ty * 8];
            float4 a1 = *(const float4*)&As[k][ty * 8 + 4];
            ulonglong2 bp = *(const ulonglong2*)&Bs[k][tx * 8];
            ulonglong2 bq = *(const ulonglong2*)&Bs[k][tx * 8 + 4];
            float aa[8] = {a0.x, a0.y, a0.z, a0.w, a1.x, a1.y, a1.z, a1.w};
            u64 ap[8];
#pragma unroll
            for (int i = 0; i < 8; i++) {
                u32 ab = __float_as_uint(aa[i]);
                PACK2(ap[i], ab, ab);
            }
#pragma unroll
            for (int i = 0; i < 8; i++) {
                FMA2(acc[i][0], ap[i], bp.x);
                FMA2(acc[i][1], ap[i], bp.y);
                FMA2(acc[i][2], ap[i], bq.x);
                FMA2(acc[i][3], ap[i], bq.y);
            }
        }
        __syncthreads();
    }
#pragma unroll
    for (int i = 0; i < 8; i++) {
        float o[8];
#pragma unroll
        for (int j = 0; j < 4; j++) {
            u32 lo, hi;
            UNPK2(lo, hi, acc[i][j]);
            o[2 * j]     = __uint_as_float(lo);
            o[2 * j + 1] = __uint_as_float(hi);
        }
        float4 o0 = {o[0], o[1], o[2], o[3]};
        float4 o1 = {o[4], o[5], o[6], o[7]};
        float* dst = &g_Iext[(size_t)(m0 + ty * 8 + i) * NH + n0 + tx * 8];
        *(float4*)dst = o0;
        *(float4*)(dst + 4) = o1;
    }
}

// -------- distributed grid barrier: release-atomic arrive, 16 counters --------
__device__ __forceinline__ void grid_sync(int step, int cta) {
    __syncthreads();
    if (threadIdx.x == 0) {
        asm volatile("red.release.gpu.global.add.u32 [%0], 1;"
                     :: "l"(&g_bars[cta & (NCTR - 1)][0]) : "memory");
    }
    if (threadIdx.x < NCTR) {
        const unsigned target = (unsigned)(step + 1) * CPC;
        unsigned cur;
        do {
            asm volatile("ld.global.acquire.gpu.u32 %0, [%1];"
                         : "=r"(cur) : "l"(&g_bars[threadIdx.x][0]));
        } while (cur < target);
    }
    __syncthreads();
}

#define RSTAGE(M, NHALF)                                                        \
    if (ln & (M)) {                                                             \
        _Pragma("unroll")                                                       \
        for (int i = 0; i < (NHALF); i++) {                                     \
            float tmp = a[i]; a[i] = a[i + (NHALF)]; a[i + (NHALF)] = tmp;      \
        }                                                                       \
    }                                                                           \
    _Pragma("unroll")                                                           \
    for (int i = 0; i < (NHALF); i++)                                           \
        a[i] += __shfl_xor_sync(0xffffffffu, a[i + (NHALF)], (M));

// -------- Phase B: persistent scan --------
__global__ __launch_bounds__(256, 1) void scan_kernel(const float* __restrict__ Wrec) {
    __shared__ float wt[8 * NH];

    const int tid = threadIdx.x;
    const int w  = tid >> 5;
    const int ln = tid & 31;
    const int c  = blockIdx.x;
    const int h0 = c * 8;
    const int bg = w >> 1;
    const int hg = w & 1;

    {
        const float4* src = (const float4*)(Wrec + (size_t)h0 * NH);
#pragma unroll
        for (int i = 0; i < 8; i++)
            ((float4*)wt)[tid + i * 256] = src[tid + i * 256];
    }
    __syncthreads();

    const int b = 8 * bg + (ln >> 2);
    const int h = h0 + 4 * hg + (ln & 3);
    const float* wbase = wt + (4 * hg) * NH + 4 * ln;

    float v = V_RST, a0 = 0.f, a1 = 0.f, ref = 0.f, hs = 0.f, psc = 0.f;
    int cnt = 0;
    float Iv = __ldcg(&g_Iext[(size_t)b * NH + h]);

    for (int t = 0; t < T_STEPS; t++) {
        if (t > 0) {
            const char* sp = (const char*)g_spk16[(t - 1) & 1];
            u64 acc[32];
#pragma unroll
            for (int i = 0; i < 32; i++) acc[i] = 0ull;

            // prefetch-depth-2 register pipeline over 8 k-sub-slices
            uint2 s0[8], s1[8], s2[8];
#pragma unroll
            for (int bb = 0; bb < 8; bb++)
                s0[bb] = __ldcg((const uint2*)(sp + (8 * bg + bb) * (NH * 2) + 8 * ln));
#pragma unroll
            for (int bb = 0; bb < 8; bb++)
                s1[bb] = __ldcg((const uint2*)(sp + (8 * bg + bb) * (NH * 2) + 8 * ln + 256));

#pragma unroll
            for (int u = 0; u < 8; u++) {
                if (u < 6) {
#pragma unroll
                    for (int bb = 0; bb < 8; bb++)
                        s2[bb] = __ldcg((const uint2*)(sp + (8 * bg + bb) * (NH * 2)
                                                          + 8 * ln + 256 * (u + 2)));
                }
                u64 p0[8], p1[8];
#pragma unroll
                for (int bb = 0; bb < 8; bb++) {
                    PACK2(p0[bb], s0[bb].x << 16, s0[bb].x & 0xFFFF0000u);
                    PACK2(p1[bb], s0[bb].y << 16, s0[bb].y & 0xFFFF0000u);
                }
#pragma unroll
                for (int hh = 0; hh < 4; hh++) {
                    ulonglong2 wv = *(const ulonglong2*)(wbase + hh * NH + 128 * u);
#pragma unroll
                    for (int bb = 0; bb < 8; bb++) {
                        FMA2(acc[bb * 4 + hh], p0[bb], wv.x);
                        FMA2(acc[bb * 4 + hh], p1[bb], wv.y);
                    }
                }
#pragma unroll
                for (int bb = 0; bb < 8; bb++) { s0[bb] = s1[bb]; s1[bb] = s2[bb]; }
            }

            float a[32];
#pragma unroll
            for (int i = 0; i < 32; i++) {
                u32 lo, hi;
                UNPK2(lo, hi, acc[i]);
                a[i] = __uint_as_float(lo) + __uint_as_float(hi);
            }
            RSTAGE(16, 16)
            RSTAGE(8, 8)
            RSTAGE(4, 4)
            RSTAGE(2, 2)
            RSTAGE(1, 1)
            float rec = a[0];

            hs  = D_SYN * hs + rec;
            psc = D_SYN * psc + hs;
        }

        float I = Iv + psc;
        a0 *= D_A0;
        a1 *= D_A1;
        v = v + ((V_RST - v) * (1.0f / 20.0f) + (I + a0 + a1) * 0.5f);
        bool in_ref = ref > 0.0f;
        if (in_ref) v = V_RST;
        float spike = (!in_ref && v >= V_TH) ? 1.0f : 0.0f;
        unsigned short s16;
        if (spike > 0.0f) {
            v = V_RST; a0 += 1.0f; a1 -= 2.0f; ref = 2.0f; cnt++;
            s16 = 0x3F80;
        } else {
            ref = fmaxf(ref - 1.0f, 0.0f);
            s16 = 0;
        }
        g_spk16[t & 1][b * NH + h] = s16;

        int tn = (t < T_STEPS - 1) ? t + 1 : t;
        Iv = __ldcg(&g_Iext[((size_t)tn * BATCH + b) * NH + h]);

        grid_sync(t, c);
    }
    g_rate[b * NH + h] = (float)cnt * 0.001f;
}

// -------- Phase C --------
__global__ __launch_bounds__(256) void out_kernel(const float* __restrict__ Wout,
                                                  float* __restrict__ out) {
    int gw   = (blockIdx.x * blockDim.x + threadIdx.x) >> 5;
    int lane = threadIdx.x & 31;
    int b = gw >> 8;
    int o = gw & 255;
    const float* r = &g_rate[b * NH];
    const float* wp = &Wout[(size_t)o * NH];
    float s = 0.f;
    for (int hh = lane; hh < NH; hh += 32) s += r[hh] * wp[hh];
#pragma unroll
    for (int off = 16; off; off >>= 1) s += __shfl_down_sync(0xffffffffu, s, off);
    if (lane == 0) out[b * NO + o] = s;
}

// -------- launch --------
extern "C" void kernel_launch(void* const* d_in, const int* in_sizes, int n_in,
                              void* d_out, int out_size) {
    const float* x = nullptr;
    const float* W_in = nullptr;
    const float* W_rec = nullptr;
    const float* W_out = nullptr;
    for (int i = 0; i < n_in; i++) {
        switch (in_sizes[i]) {
            case T_STEPS * BATCH * NI: x     = (const float*)d_in[i]; break;
            case NH * NI:              W_in  = (const float*)d_in[i]; break;
            case NH * NH:              W_rec = (const float*)d_in[i]; break;
            case NO * NH:              W_out = (const float*)d_in[i]; break;
        }
    }
    float* out = (float*)d_out;

    // launch index:      0
    init_kernel<<<1, 32>>>();

    // launch index:      1
    dim3 g1(NH / BN, (T_STEPS * BATCH) / BM);   // (8, 250)
    gemm_in_kernel<<<g1, 256>>>(x, W_in);

    // pad launches 2,3,4 (idempotent) so scan_kernel is launch index 5 for ncu -s5
    init_kernel<<<1, 32>>>();
    init_kernel<<<1, 32>>>();
    init_kernel<<<1, 32>>>();

    // launch index:      5  (ncu captures this one)
    scan_kernel<<<NBLK, 256>>>(W_rec);

    // launch index:      6
    out_kernel<<<(BATCH * NO * 32) / 256, 256>>>(W_out, out);
}